// round 1
// baseline (speedup 1.0000x reference)
#include <cuda_runtime.h>

// Problem constants
#define B_  4096
#define T_  512
#define I_  15
#define H_  64
#define GROUPS 8          // 64-thread groups per block
#define RPT 4             // batch rows per group
#define THREADS (GROUPS * 64)          // 512
#define ROWS_PER_BLOCK (GROUPS * RPT)  // 32
#define NBLOCKS (B_ / ROWS_PER_BLOCK)  // 128

typedef unsigned long long ull;

// packed fp32x2 FMA: d.lo += a.lo*b.lo; d.hi += a.hi*b.hi  (sm_100+)
__device__ __forceinline__ void ffma2(ull &d, ull a, ull b) {
    asm("fma.rn.f32x2 %0, %1, %2, %0;" : "+l"(d) : "l"(a), "l"(b));
}
__device__ __forceinline__ ull pack2(float a, float b) {
    ull r; asm("mov.b64 %0, {%1, %2};" : "=l"(r) : "f"(a), "f"(b)); return r;
}
__device__ __forceinline__ float2 unpack2(ull v) {
    float2 f; asm("mov.b64 {%0, %1}, %2;" : "=f"(f.x), "=f"(f.y) : "l"(v)); return f;
}
// Accurate-enough tanh: 2 MUFU ops, ~1e-6 rel error.
// tanh(x) = (e-1)/(e+1), e = exp(2x) = 2^(x * 2*log2(e))
__device__ __forceinline__ float fast_tanh(float x) {
    float e; asm("ex2.approx.f32 %0, %1;" : "=f"(e) : "f"(x * 2.8853900817779268f));
    float r; asm("rcp.approx.f32 %0, %1;" : "=f"(r) : "f"(e + 1.0f));
    return (e - 1.0f) * r;
}

__global__ void __launch_bounds__(THREADS, 1) rnn_fused_kernel(
    const float* __restrict__ x,     // [B, T, I]
    const float* __restrict__ W_ih,  // [H, I]
    const float* __restrict__ W_hh,  // [H, H]
    const float* __restrict__ b_ih,  // [H]
    const float* __restrict__ b_hh,  // [H]
    const float* __restrict__ fc_w,  // [O=1, H]
    const float* __restrict__ fc_b,  // [O=1]
    float* __restrict__ out)         // [B, 1]
{
    __shared__ float hbuf[2][GROUPS][RPT][H_];   // ping-pong hidden state, 16 KB
    __shared__ float xbuf[2][GROUPS][RPT][16];   // staged x_t (15 + zero pad), 4 KB
    __shared__ float red [GROUPS][RPT][2];       // head reduction partials

    const int tid  = threadIdx.x;
    const int gid  = tid >> 6;        // group 0..7
    const int jj   = tid & 63;        // output index this thread owns
    const int row0 = blockIdx.x * ROWS_PER_BLOCK + gid * RPT;

    // ---- Load weights into registers ----
    // W_hh row jj as 32 packed (W[jj][2k], W[jj][2k+1]) pairs. Row is 256B aligned.
    ull whh[H_ / 2];
    const ull* wrow = (const ull*)(W_hh + jj * H_);
    #pragma unroll
    for (int k = 0; k < H_ / 2; ++k) whh[k] = wrow[k];

    // W_ih row jj (15 floats, odd offset -> scalar loads, pad to 16)
    ull wih[8];
    #pragma unroll
    for (int p = 0; p < 7; ++p)
        wih[p] = pack2(W_ih[jj * I_ + 2 * p], W_ih[jj * I_ + 2 * p + 1]);
    wih[7] = pack2(W_ih[jj * I_ + 14], 0.0f);

    const float bias = b_ih[jj] + b_hh[jj];
    const float fcw  = fc_w[jj];

    // ---- Init smem: h0 = 0, stage x(t=0), zero the pad column ----
    const int  r_idx = jj / 15, i_idx = jj % 15;   // lanes 0..59 cover RPT*15 x elems
    const bool has_x = (jj < 60);
    const float* xp = x + ((long)(row0 + r_idx) * T_) * I_ + i_idx;
    if (has_x) xbuf[0][gid][r_idx][i_idx] = xp[0];
    if (jj < RPT) { xbuf[0][gid][jj][15] = 0.0f; xbuf[1][gid][jj][15] = 0.0f; }
    #pragma unroll
    for (int r = 0; r < RPT; ++r) hbuf[0][gid][r][jj] = 0.0f;
    xp += I_;   // now points at t=1 for this lane's (row, i)
    __syncthreads();

    // ---- Recurrence ----
    float hn[RPT];
    for (int t = 0; t < T_; ++t) {
        const int cur = t & 1, nxt = cur ^ 1;

        // prefetch x for t+1 into a register (hidden behind this step's math)
        float xn = 0.0f;
        const bool pf = has_x && (t + 1 < T_);
        if (pf) { xn = __ldg(xp); xp += I_; }

        const ulonglong2* hc = (const ulonglong2*)&hbuf[cur][gid][0][0]; // [RPT][16]
        const ulonglong2* xc = (const ulonglong2*)&xbuf[cur][gid][0][0]; // [RPT][4]

        ull acc[RPT];
        #pragma unroll
        for (int r = 0; r < RPT; ++r) acc[r] = 0ULL;

        // input projection: 16 padded floats per row = 4 x 128-bit broadcast LDS
        #pragma unroll
        for (int ii = 0; ii < 4; ++ii) {
            #pragma unroll
            for (int r = 0; r < RPT; ++r) {
                ulonglong2 v = xc[r * 4 + ii];
                ffma2(acc[r], v.x, wih[2 * ii]);
                ffma2(acc[r], v.y, wih[2 * ii + 1]);
            }
        }
        // recurrent matvec: 64 floats per row = 16 x 128-bit broadcast LDS
        #pragma unroll
        for (int kk = 0; kk < 16; ++kk) {
            #pragma unroll
            for (int r = 0; r < RPT; ++r) {
                ulonglong2 v = hc[r * 16 + kk];
                ffma2(acc[r], v.x, whh[2 * kk]);
                ffma2(acc[r], v.y, whh[2 * kk + 1]);
            }
        }
        #pragma unroll
        for (int r = 0; r < RPT; ++r) {
            float2 f = unpack2(acc[r]);
            hn[r] = fast_tanh(f.x + f.y + bias);
        }

        // write next-state buffers, then one barrier per step.
        // Safe: readers of buf[cur] at step t are ordered before writers of
        // buf[cur] at step t+1 by this barrier (ping-pong proof in analysis).
        #pragma unroll
        for (int r = 0; r < RPT; ++r) hbuf[nxt][gid][r][jj] = hn[r];
        if (pf) xbuf[nxt][gid][r_idx][i_idx] = xn;
        __syncthreads();
    }

    // ---- Linear head: out[row] = sum_j h_T[j] * fc_w[j] + fc_b ----
    float part[RPT];
    #pragma unroll
    for (int r = 0; r < RPT; ++r) {
        part[r] = hn[r] * fcw;
        #pragma unroll
        for (int o = 16; o > 0; o >>= 1)
            part[r] += __shfl_down_sync(0xffffffffu, part[r], o);
    }
    if ((jj & 31) == 0) {
        #pragma unroll
        for (int r = 0; r < RPT; ++r) red[gid][r][jj >> 5] = part[r];
    }
    __syncthreads();
    if (jj < RPT)
        out[row0 + jj] = red[gid][jj][0] + red[gid][jj][1] + fc_b[0];
}

extern "C" void kernel_launch(void* const* d_in, const int* in_sizes, int n_in,
                              void* d_out, int out_size) {
    const float* x    = (const float*)d_in[0];
    const float* W_ih = (const float*)d_in[1];
    const float* W_hh = (const float*)d_in[2];
    const float* b_ih = (const float*)d_in[3];
    const float* b_hh = (const float*)d_in[4];
    const float* fc_w = (const float*)d_in[5];
    const float* fc_b = (const float*)d_in[6];
    rnn_fused_kernel<<<NBLOCKS, THREADS>>>(x, W_ih, W_hh, b_ih, b_hh,
                                           fc_w, fc_b, (float*)d_out);
}

// round 2
// speedup vs baseline: 1.1463x; 1.1463x over previous
#include <cuda_runtime.h>

// Problem constants
#define T_  512
#define I_  15
#define H_  64
#define RPT 4                 // batch rows per block
#define THREADS 128           // 64 output-pairs (2 lanes each)
#define NBLOCKS (4096 / RPT)  // 1024
#define HROW 72               // 64 h + skew pad (high half at float 36)

typedef unsigned long long ull;

// packed fp32x2 FMA: d.lo += a.lo*b.lo; d.hi += a.hi*b.hi  (sm_100+)
__device__ __forceinline__ void ffma2(ull &d, ull a, ull b) {
    asm("fma.rn.f32x2 %0, %1, %2, %0;" : "+l"(d) : "l"(a), "l"(b));
}
__device__ __forceinline__ ull pack2(float a, float b) {
    ull r; asm("mov.b64 %0, {%1, %2};" : "=l"(r) : "f"(a), "f"(b)); return r;
}
__device__ __forceinline__ float2 unpack2(ull v) {
    float2 f; asm("mov.b64 {%0, %1}, %2;" : "=f"(f.x), "=f"(f.y) : "l"(v)); return f;
}
// Accurate tanh, 2 MUFU: tanh(x) = (e-1)/(e+1), e = 2^(x*2*log2(e))
__device__ __forceinline__ float fast_tanh(float x) {
    float e; asm("ex2.approx.f32 %0, %1;" : "=f"(e) : "f"(x * 2.8853900817779268f));
    float r; asm("rcp.approx.f32 %0, %1;" : "=f"(r) : "f"(e + 1.0f));
    return (e - 1.0f) * r;
}

__global__ void __launch_bounds__(THREADS, 7) rnn_fused_kernel(
    const float* __restrict__ x,     // [B, T, I]
    const float* __restrict__ W_ih,  // [H, I]
    const float* __restrict__ W_hh,  // [H, H]
    const float* __restrict__ b_ih,  // [H]
    const float* __restrict__ b_hh,  // [H]
    const float* __restrict__ fc_w,  // [1, H]
    const float* __restrict__ fc_b,  // [1]
    float* __restrict__ out)         // [B, 1]
{
    __shared__ float hbuf[2][RPT][HROW];   // ping-pong h; cols 0-31 @ 0, 32-63 @ float 36
    __shared__ float xbuf[2][RPT][16];     // staged x_t (15 + zero pad)
    __shared__ float red[RPT][4];          // head partials per warp

    const int tid  = threadIdx.x;
    const int jj   = tid >> 1;        // output 0..63 (pair id)
    const int kh   = tid & 1;         // k-half: 0 -> k[0,32), 1 -> k[32,64)
    const int lane = tid & 31;
    const int wrp  = tid >> 5;
    const int row0 = blockIdx.x * RPT;

    // ---- Weights to registers (half of k-range per lane) ----
    ull whh[16];
    const ull* wrow = (const ull*)(W_hh + jj * H_ + kh * 32);  // 8B-aligned
    #pragma unroll
    for (int k = 0; k < 16; ++k) whh[k] = wrow[k];

    ull wih[4];   // even lane: inputs 0..7, odd: 8..14 + zero pad
    #pragma unroll
    for (int p = 0; p < 4; ++p) {
        int i0 = kh * 8 + 2 * p;
        float a = W_ih[jj * I_ + i0];
        float b = (i0 + 1 < I_) ? W_ih[jj * I_ + i0 + 1] : 0.0f;
        wih[p] = pack2(a, b);
    }

    const float bias = b_ih[jj] + b_hh[jj];
    const float fcw  = fc_w[jj];

    // Owned rows for tanh/STS: even lane rows {0,1}, odd rows {2,3}
    const int rA = kh * 2, rB = kh * 2 + 1;
    const int cidx = jj + (jj >= 32 ? 4 : 0);   // skewed column

    // ---- Init: h0 = 0, stage x(t=0), zero x pad ----
    hbuf[0][rA][cidx] = 0.0f;
    hbuf[0][rB][cidx] = 0.0f;
    const int  sr = tid / 15, si = tid % 15;
    const bool stg = (tid < 60);
    const float* xp = x + ((long)(row0 + sr) * T_) * I_ + si;
    if (stg) xbuf[0][sr][si] = *xp;
    if (tid < RPT) { xbuf[0][tid][15] = 0.0f; xbuf[1][tid][15] = 0.0f; }
    xp += I_;
    __syncthreads();

    // ---- Recurrence ----
    float hn0 = 0.0f, hn1 = 0.0f;
    for (int t = 0; t < T_; ++t) {
        const int cur = t & 1, nxt = cur ^ 1;

        // prefetch x for t+1 (hidden behind this step's math)
        float xn = 0.0f;
        const bool pf = stg && (t + 1 < T_);
        if (pf) { xn = __ldg(xp); xp += I_; }

        // broadcast-load bases for this lane's k-half (16B aligned)
        const ulonglong2* hb2 = (const ulonglong2*)&hbuf[cur][0][kh * 36];
        const ulonglong2* xb2 = (const ulonglong2*)&xbuf[cur][0][kh * 8];

        ull acc[RPT] = {0ULL, 0ULL, 0ULL, 0ULL};

        // input projection: 2 x 128-bit LDS per row (this half)
        #pragma unroll
        for (int q = 0; q < 2; ++q) {
            #pragma unroll
            for (int r = 0; r < RPT; ++r) {
                ulonglong2 v = xb2[r * 4 + q];       // row stride 16 floats
                ffma2(acc[r], v.x, wih[2 * q]);
                ffma2(acc[r], v.y, wih[2 * q + 1]);
            }
        }
        // recurrent matvec: 8 x 128-bit LDS per row (this half of k)
        #pragma unroll
        for (int q = 0; q < 8; ++q) {
            #pragma unroll
            for (int r = 0; r < RPT; ++r) {
                ulonglong2 v = hb2[r * 18 + q];      // row stride 72 floats
                ffma2(acc[r], v.x, whh[2 * q]);
                ffma2(acc[r], v.y, whh[2 * q + 1]);
            }
        }

        // combine halves across the lane pair
        float tot[RPT];
        #pragma unroll
        for (int r = 0; r < RPT; ++r) {
            float2 f = unpack2(acc[r]);
            float s = f.x + f.y;
            tot[r] = s + __shfl_xor_sync(0xffffffffu, s, 1);
        }

        hn0 = fast_tanh(tot[rA] + bias);
        hn1 = fast_tanh(tot[rB] + bias);
        hbuf[nxt][rA][cidx] = hn0;
        hbuf[nxt][rB][cidx] = hn1;
        if (pf) xbuf[nxt][sr][si] = xn;
        __syncthreads();
    }

    // ---- Head: out[row] = sum_j h_T[row][j] * fc_w[j] + fc_b ----
    float p0 = hn0 * fcw, p1 = hn1 * fcw;   // even lane: rows 0,1; odd: rows 2,3
    #pragma unroll
    for (int o = 2; o <= 16; o <<= 1) {     // reduce over same-parity lanes
        p0 += __shfl_down_sync(0xffffffffu, p0, o);
        p1 += __shfl_down_sync(0xffffffffu, p1, o);
    }
    if (lane == 0) { red[0][wrp] = p0; red[1][wrp] = p1; }   // rows 0,1
    if (lane == 1) { red[2][wrp] = p0; red[3][wrp] = p1; }   // rows 2,3
    __syncthreads();
    if (tid < RPT)
        out[row0 + tid] = red[tid][0] + red[tid][1] + red[tid][2] + red[tid][3]
                        + fc_b[0];
}

extern "C" void kernel_launch(void* const* d_in, const int* in_sizes, int n_in,
                              void* d_out, int out_size) {
    const float* x    = (const float*)d_in[0];
    const float* W_ih = (const float*)d_in[1];
    const float* W_hh = (const float*)d_in[2];
    const float* b_ih = (const float*)d_in[3];
    const float* b_hh = (const float*)d_in[4];
    const float* fc_w = (const float*)d_in[5];
    const float* fc_b = (const float*)d_in[6];
    rnn_fused_kernel<<<NBLOCKS, THREADS>>>(x, W_ih, W_hh, b_ih, b_hh,
                                           fc_w, fc_b, (float*)d_out);
}

// round 3
// speedup vs baseline: 1.1578x; 1.0101x over previous
#include <cuda_runtime.h>

#define T_  512
#define I_  15
#define H_  64
#define RPB 8                 // batch rows per block
#define THREADS 128
#define NBLOCKS (4096 / RPB)  // 512

typedef unsigned long long ull;

// packed fp32x2 FMA (sm_100+): d.lo += a.lo*b.lo; d.hi += a.hi*b.hi
__device__ __forceinline__ void ffma2(ull &d, ull a, ull b) {
    asm("fma.rn.f32x2 %0, %1, %2, %0;" : "+l"(d) : "l"(a), "l"(b));
}
__device__ __forceinline__ ull pack2(float a, float b) {
    ull r; asm("mov.b64 %0, {%1, %2};" : "=l"(r) : "f"(a), "f"(b)); return r;
}
__device__ __forceinline__ float2 unpack2(ull v) {
    float2 f; asm("mov.b64 {%0, %1}, %2;" : "=f"(f.x), "=f"(f.y) : "l"(v)); return f;
}
// Accurate tanh, 2 MUFU: tanh(x) = (e-1)/(e+1), e = 2^(x*2*log2(e))
__device__ __forceinline__ float fast_tanh(float x) {
    float e; asm("ex2.approx.f32 %0, %1;" : "=f"(e) : "f"(x * 2.8853900817779268f));
    float r; asm("rcp.approx.f32 %0, %1;" : "=f"(r) : "f"(e + 1.0f));
    return (e - 1.0f) * r;
}

// Interleaved half layout inside one h row (64 floats):
//   h[kh*32 + q*4 + e]  lives at float offset  q*8 + kh*4 + e   (q=0..7)
// -> a warp's even lanes (kh=0) and odd lanes (kh=1) read two 16B chunks in
//    the SAME 128B line, disjoint banks: 1 wavefront per LDS.128.
// x rows (16 floats, 15 real + pad): h[kh*8 + q*4 + e] at q*8 + kh*4 + e (q=0..1)

__global__ void __launch_bounds__(THREADS, 4) rnn_fused_kernel(
    const float* __restrict__ x,     // [B, T, I]
    const float* __restrict__ W_ih,  // [H, I]
    const float* __restrict__ W_hh,  // [H, H]
    const float* __restrict__ b_ih,  // [H]
    const float* __restrict__ b_hh,  // [H]
    const float* __restrict__ fc_w,  // [1, H]
    const float* __restrict__ fc_b,  // [1]
    float* __restrict__ out)         // [B, 1]
{
    __shared__ float hbuf[2][RPB][H_];   // ping-pong hidden state (interleaved)
    __shared__ float xbuf[2][RPB][16];   // staged x_t (interleaved, pos 15 = 0)
    __shared__ float red[RPB][2];        // head partials

    const int tid  = threadIdx.x;
    const int pair = tid >> 1;       // 0..63
    const int kh   = tid & 1;        // k-half: 0 -> k[0,32), 1 -> k[32,64)
    const int jj   = pair & 31;      // base output column 0..31
    const int rg   = pair >> 5;      // row-group 0/1 (rows rg*4 .. rg*4+3)
    const int lane = tid & 31;
    const int wrp  = tid >> 5;
    const int row0 = blockIdx.x * RPB;

    const int j0 = jj, j1 = jj + 32; // this pair's two outputs

    // ---- Weights to registers ----
    // W_hh rows j0/j1, this lane's k-half: 16 ull each (8B-aligned, 128B chunks)
    ull whhA[16], whhB[16];
    {
        const ull* w0 = (const ull*)(W_hh + j0 * H_ + kh * 32);
        const ull* w1 = (const ull*)(W_hh + j1 * H_ + kh * 32);
        #pragma unroll
        for (int i = 0; i < 16; ++i) { whhA[i] = w0[i]; whhB[i] = w1[i]; }
    }
    // W_ih rows j0/j1, this lane's 8-input half (pad idx 15 with 0)
    ull wihA[4], wihB[4];
    #pragma unroll
    for (int q = 0; q < 2; ++q) {
        #pragma unroll
        for (int s = 0; s < 2; ++s) {
            int i0 = kh * 8 + q * 4 + 2 * s;
            float a0 = (i0     < I_) ? W_ih[j0 * I_ + i0]     : 0.0f;
            float b0 = (i0 + 1 < I_) ? W_ih[j0 * I_ + i0 + 1] : 0.0f;
            float a1 = (i0     < I_) ? W_ih[j1 * I_ + i0]     : 0.0f;
            float b1 = (i0 + 1 < I_) ? W_ih[j1 * I_ + i0 + 1] : 0.0f;
            wihA[2 * q + s] = pack2(a0, b0);
            wihB[2 * q + s] = pack2(a1, b1);
        }
    }

    const int  myj  = kh ? j1 : j0;          // the j this lane tanh's/stores
    const float bias = b_ih[myj] + b_hh[myj];
    const float fcw  = fc_w[myj];
    // store offset of h[myj] inside a row (interleaved layout, jh = kh)
    const int hoff = (jj >> 2) * 8 + kh * 4 + (jj & 3);

    // ---- Init: h0 = 0, stage x(t=0), zero x pad ----
    #pragma unroll
    for (int i = 0; i < (RPB * H_) / THREADS; ++i)
        ((float*)hbuf[0])[tid + i * THREADS] = 0.0f;
    const int  sr = tid / 15, si = tid % 15;     // staging lanes 0..119
    const bool stg = (tid < 120);
    const int  xoff = ((si & 7) >> 2) * 8 + (si >> 3) * 4 + (si & 3);
    const float* xp = x + ((long)(row0 + sr) * T_) * I_ + si;
    if (stg) xbuf[0][sr][xoff] = *xp;
    if (tid < RPB) { xbuf[0][tid][15] = 0.0f; xbuf[1][tid][15] = 0.0f; }
    xp += I_;
    __syncthreads();

    // ---- Recurrence ----
    float hn[4];
    for (int t = 0; t < T_; ++t) {
        const int cur = t & 1, nxt = cur ^ 1;

        // prefetch x for t+1 (hidden behind this step's math)
        float xn = 0.0f;
        const bool pf = stg && (t + 1 < T_);
        if (pf) { xn = __ldg(xp); xp += I_; }

        // 16B chunk pointers for this lane: chunk(r,q) at base + r*stride + q*2
        const ulonglong2* hb2 = (const ulonglong2*)hbuf[cur] + (rg * 4) * 16 + kh;
        const ulonglong2* xb2 = (const ulonglong2*)xbuf[cur] + (rg * 4) * 4  + kh;

        ull acc0[4] = {0, 0, 0, 0};
        ull acc1[4] = {0, 0, 0, 0};

        // input projection: 2 chunks per row, each LDS feeds both outputs
        #pragma unroll
        for (int q = 0; q < 2; ++q) {
            #pragma unroll
            for (int r = 0; r < 4; ++r) {
                ulonglong2 v = xb2[r * 4 + q * 2];
                ffma2(acc0[r], v.x, wihA[2 * q]);
                ffma2(acc0[r], v.y, wihA[2 * q + 1]);
                ffma2(acc1[r], v.x, wihB[2 * q]);
                ffma2(acc1[r], v.y, wihB[2 * q + 1]);
            }
        }
        // recurrent matvec: 8 chunks per row, 4 ffma2 per LDS.128
        #pragma unroll
        for (int q = 0; q < 8; ++q) {
            #pragma unroll
            for (int r = 0; r < 4; ++r) {
                ulonglong2 v = hb2[r * 16 + q * 2];
                ffma2(acc0[r], v.x, whhA[2 * q]);
                ffma2(acc0[r], v.y, whhA[2 * q + 1]);
                ffma2(acc1[r], v.x, whhB[2 * q]);
                ffma2(acc1[r], v.y, whhB[2 * q + 1]);
            }
        }

        // combine k-halves across the lane pair; each lane keeps its own j
        #pragma unroll
        for (int r = 0; r < 4; ++r) {
            float2 f0 = unpack2(acc0[r]);
            float2 f1 = unpack2(acc1[r]);
            float s0 = f0.x + f0.y;
            float s1 = f1.x + f1.y;
            s0 += __shfl_xor_sync(0xffffffffu, s0, 1);   // total for j0
            s1 += __shfl_xor_sync(0xffffffffu, s1, 1);   // total for j1
            float sown = kh ? s1 : s0;
            hn[r] = fast_tanh(sown + bias);
            hbuf[nxt][rg * 4 + r][hoff] = hn[r];
        }
        if (pf) xbuf[nxt][sr][xoff] = xn;
        __syncthreads();
    }

    // ---- Head: out[row] = sum_j h_T[row][j] * fc_w[j] + fc_b ----
    // Warp w covers rows rg*4..+3 with j-set {jj-range} ∪ {+32}: 32 distinct j.
    float p[4];
    #pragma unroll
    for (int r = 0; r < 4; ++r) {
        p[r] = hn[r] * fcw;
        #pragma unroll
        for (int o = 16; o > 0; o >>= 1)
            p[r] += __shfl_xor_sync(0xffffffffu, p[r], o);
    }
    if (lane == 0) {
        #pragma unroll
        for (int r = 0; r < 4; ++r)
            red[(wrp >> 1) * 4 + r][wrp & 1] = p[r];
    }
    __syncthreads();
    if (tid < RPB)
        out[row0 + tid] = red[tid][0] + red[tid][1] + fc_b[0];
}

extern "C" void kernel_launch(void* const* d_in, const int* in_sizes, int n_in,
                              void* d_out, int out_size) {
    const float* x    = (const float*)d_in[0];
    const float* W_ih = (const float*)d_in[1];
    const float* W_hh = (const float*)d_in[2];
    const float* b_ih = (const float*)d_in[3];
    const float* b_hh = (const float*)d_in[4];
    const float* fc_w = (const float*)d_in[5];
    const float* fc_b = (const float*)d_in[6];
    rnn_fused_kernel<<<NBLOCKS, THREADS>>>(x, W_ih, W_hh, b_ih, b_hh,
                                           fc_w, fc_b, (float*)d_out);
}

// round 4
// speedup vs baseline: 1.1991x; 1.0357x over previous
#include <cuda_runtime.h>

#define T_  512
#define I_  15
#define H_  64
#define RPB 4                 // batch rows per block
#define THREADS 64            // 2 warps = minimal W_hh-resident unit
#define NBLOCKS (4096 / RPB)  // 1024

typedef unsigned long long ull;

// packed fp32x2 FMA (sm_100+): d.lo += a.lo*b.lo; d.hi += a.hi*b.hi
__device__ __forceinline__ void ffma2(ull &d, ull a, ull b) {
    asm("fma.rn.f32x2 %0, %1, %2, %0;" : "+l"(d) : "l"(a), "l"(b));
}
__device__ __forceinline__ ull pack2(float a, float b) {
    ull r; asm("mov.b64 %0, {%1, %2};" : "=l"(r) : "f"(a), "f"(b)); return r;
}
__device__ __forceinline__ float2 unpack2(ull v) {
    float2 f; asm("mov.b64 {%0, %1}, %2;" : "=f"(f.x), "=f"(f.y) : "l"(v)); return f;
}
// Accurate tanh, 2 MUFU: tanh(x) = (e-1)/(e+1), e = 2^(x*2*log2(e))
__device__ __forceinline__ float fast_tanh(float x) {
    float e; asm("ex2.approx.f32 %0, %1;" : "=f"(e) : "f"(x * 2.8853900817779268f));
    float r; asm("rcp.approx.f32 %0, %1;" : "=f"(r) : "f"(e + 1.0f));
    return (e - 1.0f) * r;
}

// Interleaved half layout inside one h row (64 floats):
//   h[kh*32 + q*4 + e]  lives at float offset  q*8 + kh*4 + e   (q=0..7)
// -> even lanes (kh=0) and odd lanes (kh=1) read 16B chunks in the SAME 128B
//    line, disjoint banks: 1 wavefront per LDS.128.
// x rows (16 floats, 15 real + pad): x[kh*8 + q*4 + e] at q*8 + kh*4 + e (q=0..1)

__global__ void __launch_bounds__(THREADS, 8) rnn_fused_kernel(
    const float* __restrict__ x,     // [B, T, I]
    const float* __restrict__ W_ih,  // [H, I]
    const float* __restrict__ W_hh,  // [H, H]
    const float* __restrict__ b_ih,  // [H]
    const float* __restrict__ b_hh,  // [H]
    const float* __restrict__ fc_w,  // [1, H]
    const float* __restrict__ fc_b,  // [1]
    float* __restrict__ out)         // [B, 1]
{
    __shared__ float hbuf[2][RPB][H_];   // ping-pong hidden state (interleaved)
    __shared__ float xbuf[2][RPB][16];   // staged x_t (interleaved, pos 15 = 0)
    __shared__ float red[RPB][2];        // head partials per warp

    const int tid  = threadIdx.x;
    const int jj   = tid >> 1;       // pair id = base output column 0..31
    const int kh   = tid & 1;        // k-half: 0 -> k[0,32), 1 -> k[32,64)
    const int lane = tid & 31;
    const int wrp  = tid >> 5;
    const int row0 = blockIdx.x * RPB;

    const int j0 = jj, j1 = jj + 32; // this pair's two outputs

    // ---- Weights to registers ----
    ull whhA[16], whhB[16];          // W_hh rows j0/j1, this lane's k-half
    {
        const ull* w0 = (const ull*)(W_hh + j0 * H_ + kh * 32);
        const ull* w1 = (const ull*)(W_hh + j1 * H_ + kh * 32);
        #pragma unroll
        for (int i = 0; i < 16; ++i) { whhA[i] = w0[i]; whhB[i] = w1[i]; }
    }
    ull wihA[4], wihB[4];            // W_ih rows j0/j1, this lane's 8-input half
    #pragma unroll
    for (int q = 0; q < 2; ++q) {
        #pragma unroll
        for (int s = 0; s < 2; ++s) {
            int i0 = kh * 8 + q * 4 + 2 * s;
            float a0 = (i0     < I_) ? W_ih[j0 * I_ + i0]     : 0.0f;
            float b0 = (i0 + 1 < I_) ? W_ih[j0 * I_ + i0 + 1] : 0.0f;
            float a1 = (i0     < I_) ? W_ih[j1 * I_ + i0]     : 0.0f;
            float b1 = (i0 + 1 < I_) ? W_ih[j1 * I_ + i0 + 1] : 0.0f;
            wihA[2 * q + s] = pack2(a0, b0);
            wihB[2 * q + s] = pack2(a1, b1);
        }
    }

    const int  myj  = kh ? j1 : j0;          // the j this lane owns
    const float bias = b_ih[myj] + b_hh[myj];
    const float fcw  = fc_w[myj];
    const int hoff = (jj >> 2) * 8 + kh * 4 + (jj & 3);   // h[myj] slot in a row

    // ---- Init: h0 = 0, stage x(t=0), zero x pad ----
    #pragma unroll
    for (int i = 0; i < (RPB * H_) / THREADS; ++i)
        ((float*)hbuf[0])[tid + i * THREADS] = 0.0f;
    const int  sr = tid / 15, si = tid % 15;     // staging lanes 0..59
    const bool stg = (tid < 60);
    const int  xoff = ((si & 7) >> 2) * 8 + (si >> 3) * 4 + (si & 3);
    const float* xp = x + ((long)(row0 + sr) * T_) * I_ + si;
    if (stg) xbuf[0][sr][xoff] = *xp;
    if (tid < RPB) { xbuf[0][tid][15] = 0.0f; xbuf[1][tid][15] = 0.0f; }
    xp += I_;
    __syncthreads();

    // ---- Recurrence ----
    float hn[RPB];
    for (int t = 0; t < T_; ++t) {
        const int cur = t & 1, nxt = cur ^ 1;

        // prefetch x for t+1 (hidden behind this step's math)
        float xn = 0.0f;
        const bool pf = stg && (t + 1 < T_);
        if (pf) { xn = __ldg(xp); xp += I_; }

        // 16B chunk pointers for this lane's k-half
        const ulonglong2* hb2 = (const ulonglong2*)hbuf[cur] + kh;
        const ulonglong2* xb2 = (const ulonglong2*)xbuf[cur] + kh;

        ull acc0[RPB] = {0, 0, 0, 0};
        ull acc1[RPB] = {0, 0, 0, 0};

        // input projection: 2 chunks per row; each LDS feeds both outputs
        #pragma unroll
        for (int q = 0; q < 2; ++q) {
            #pragma unroll
            for (int r = 0; r < RPB; ++r) {
                ulonglong2 v = xb2[r * 4 + q * 2];
                ffma2(acc0[r], v.x, wihA[2 * q]);
                ffma2(acc0[r], v.y, wihA[2 * q + 1]);
                ffma2(acc1[r], v.x, wihB[2 * q]);
                ffma2(acc1[r], v.y, wihB[2 * q + 1]);
            }
        }
        // recurrent matvec: 8 chunks per row; 4 ffma2 per LDS.128
        #pragma unroll
        for (int q = 0; q < 8; ++q) {
            #pragma unroll
            for (int r = 0; r < RPB; ++r) {
                ulonglong2 v = hb2[r * 16 + q * 2];
                ffma2(acc0[r], v.x, whhA[2 * q]);
                ffma2(acc0[r], v.y, whhA[2 * q + 1]);
                ffma2(acc1[r], v.x, whhB[2 * q]);
                ffma2(acc1[r], v.y, whhB[2 * q + 1]);
            }
        }

        // combine k-halves: ONE shfl per row. Each lane sends the partial for
        // its PARTNER's j and receives the partner's partial for ITS OWN j.
        #pragma unroll
        for (int r = 0; r < RPB; ++r) {
            float2 f0 = unpack2(acc0[r]);     // partial for j0, my k-half
            float2 f1 = unpack2(acc1[r]);     // partial for j1, my k-half
            float s0 = f0.x + f0.y;
            float s1 = f1.x + f1.y;
            float s_mine  = kh ? s1 : s0;
            float s_other = kh ? s0 : s1;
            float tot = s_mine + __shfl_xor_sync(0xffffffffu, s_other, 1);
            hn[r] = fast_tanh(tot + bias);
            hbuf[nxt][r][hoff] = hn[r];
        }
        if (pf) xbuf[nxt][sr][xoff] = xn;
        __syncthreads();   // couples only 2 warps now
    }

    // ---- Head: out[row] = sum_j h_T[row][j] * fc_w[j] + fc_b ----
    // warp0 covers j 0..15 & 32..47, warp1 covers j 16..31 & 48..63.
    float p[RPB];
    #pragma unroll
    for (int r = 0; r < RPB; ++r) {
        p[r] = hn[r] * fcw;
        #pragma unroll
        for (int o = 16; o > 0; o >>= 1)
            p[r] += __shfl_xor_sync(0xffffffffu, p[r], o);
    }
    if (lane == 0) {
        #pragma unroll
        for (int r = 0; r < RPB; ++r) red[r][wrp] = p[r];
    }
    __syncthreads();
    if (tid < RPB)
        out[row0 + tid] = red[tid][0] + red[tid][1] + fc_b[0];
}

extern "C" void kernel_launch(void* const* d_in, const int* in_sizes, int n_in,
                              void* d_out, int out_size) {
    const float* x    = (const float*)d_in[0];
    const float* W_ih = (const float*)d_in[1];
    const float* W_hh = (const float*)d_in[2];
    const float* b_ih = (const float*)d_in[3];
    const float* b_hh = (const float*)d_in[4];
    const float* fc_w = (const float*)d_in[5];
    const float* fc_b = (const float*)d_in[6];
    rnn_fused_kernel<<<NBLOCKS, THREADS>>>(x, W_ih, W_hh, b_ih, b_hh,
                                           fc_w, fc_b, (float*)d_out);
}